// round 12
// baseline (speedup 1.0000x reference)
#include <cuda_runtime.h>
#include <cuda_fp16.h>

// NeuralVoxelField: trilinear interp of 2M random points into a 128^3 x16 grid.
//
// R11 (on top of R10: fp16 grid scratch, z-pair 16B gathers, half2 x/y lerp,
// lane-pair z reduce, evict-last gather policy):
//  1. output stores use st.global.wt (write-through, NO L2 allocate) so the
//     128MB output stream stops displacing the 64MB fp16 grid from L2.
//  2. 2 points per thread (p and p+half): 8 outstanding gathers/thread for
//     latency hiding; both output segments per warp remain contiguous.

constexpr int Dg = 128, Hg = 128, Wg = 128, Cg = 16;
constexpr float INV_VOXEL = 20.0f;               // 1/0.05
constexpr int NVOX   = Dg * Hg * Wg;
constexpr int NHALF  = NVOX * Cg;                // 64MB of halves
constexpr int NELEM4 = NHALF / 4;

__device__ __align__(16) __half d_grid_h[NHALF];

// ---- pass 1: fp32 grid -> fp16 scratch (streaming, DRAM-roofline) ----
__global__ __launch_bounds__(256)
void convert_kernel(const float4* __restrict__ values) {
    int i = blockIdx.x * blockDim.x + threadIdx.x;
    if (i >= NELEM4) return;
    float4 v = __ldcs(&values[i]);               // evict-first: read once
    __half2 a = __float22half2_rn(make_float2(v.x, v.y));
    __half2 b = __float22half2_rn(make_float2(v.z, v.w));
    uint2 u;
    u.x = *reinterpret_cast<unsigned int*>(&a);
    u.y = *reinterpret_cast<unsigned int*>(&b);
    *reinterpret_cast<uint2*>(&d_grid_h[(size_t)i * 4]) = u;  // want L2-resident
}

__device__ __forceinline__ unsigned long long mk_evict_last_policy() {
    unsigned long long pol;
    asm("createpolicy.fractional.L2::evict_last.b64 %0, 1.0;" : "=l"(pol));
    return pol;
}

__device__ __forceinline__ uint4 ldg_el(const __half* p, unsigned long long pol) {
    uint4 q;
    asm volatile("ld.global.nc.L2::cache_hint.v4.u32 {%0,%1,%2,%3}, [%4], %5;"
                 : "=r"(q.x), "=r"(q.y), "=r"(q.z), "=r"(q.w)
                 : "l"(p), "l"(pol));
    return q;
}

// out[i] = a[i] + (b[i]-a[i])*w   (4x half2)
__device__ __forceinline__ void lerp_h2x4(const uint4& a, const uint4& b,
                                          __half2 w, __half2* o) {
    const __half2* ah = reinterpret_cast<const __half2*>(&a);
    const __half2* bh = reinterpret_cast<const __half2*>(&b);
    #pragma unroll
    for (int i = 0; i < 4; i++)
        o[i] = __hfma2(__hsub2(bh[i], ah[i]), w, ah[i]);
}

struct PointCtx {
    int   base[4];   // 4 corner addresses (half elements)
    float wa;        // my z-weight
    float xd, yd;
};

__device__ __forceinline__ PointCtx point_setup(const float* __restrict__ points,
                                                int p, int l) {
    float x = __ldcs(&points[p * 3 + 0]) * INV_VOXEL;
    float y = __ldcs(&points[p * 3 + 1]) * INV_VOXEL;
    float z = __ldcs(&points[p * 3 + 2]) * INV_VOXEL;

    int x0 = min(max(__float2int_rd(x), 0), Dg - 1);
    int y0 = min(max(__float2int_rd(y), 0), Hg - 1);
    int z0 = min(max(__float2int_rd(z), 0), Wg - 1);
    int x1 = min(x0 + 1, Dg - 1);
    int y1 = min(y0 + 1, Hg - 1);
    int zp = min(z0, Wg - 2);

    PointCtx c;
    c.xd = x - (float)x0;
    c.yd = y - (float)y0;
    float zd = z - (float)z0;
    float w1 = (z0 == Wg - 1) ? 1.0f : zd;
    int v = l >> 1;
    c.wa = v ? w1 : (1.0f - w1);

    int zb = zp * Cg + l * 8;
    c.base[0] = ((x0 * Hg + y0) * Wg) * Cg + zb;   // 00
    c.base[1] = ((x0 * Hg + y1) * Wg) * Cg + zb;   // 01
    c.base[2] = ((x1 * Hg + y0) * Wg) * Cg + zb;   // 10
    c.base[3] = ((x1 * Hg + y1) * Wg) * Cg + zb;   // 11
    return c;
}

__device__ __forceinline__ float4 point_combine(const uint4* q, const PointCtx& c,
                                                int l) {
    __half2 yd2 = __float2half2_rn(c.yd);
    __half2 xd2 = __float2half2_rn(c.xd);

    __half2 t0[4], t1[4];
    lerp_h2x4(q[0], q[1], yd2, t0);    // @x0
    lerp_h2x4(q[2], q[3], yd2, t1);    // @x1

    float m[8];
    #pragma unroll
    for (int i = 0; i < 4; i++) {
        __half2 r = __hfma2(__hsub2(t1[i], t0[i]), xd2, t0[i]);
        float2 f = __half22float2(r);
        m[i * 2 + 0] = f.x * c.wa;
        m[i * 2 + 1] = f.y * c.wa;
    }

    float cc[8];
    #pragma unroll
    for (int i = 0; i < 8; i++)
        cc[i] = m[i] + __shfl_xor_sync(0xffffffffu, m[i], 2);

    int v = l >> 1;
    const float* s = cc + v * 4;
    return make_float4(s[0], s[1], s[2], s[3]);
}

__global__ __launch_bounds__(256, 4)
void interp_kernel(const float* __restrict__ points,
                   float4* __restrict__ out,     // (N,16) fp32 as float4
                   int n, int half)
{
    int t = blockIdx.x * blockDim.x + threadIdx.x;
    int pA = t >> 2;       // first point
    int l  = t & 3;        // lane-in-point
    if (pA >= half) return;
    int pB = pA + half;
    bool hasB = (pB < n);

    unsigned long long pol = mk_evict_last_policy();
    const __half* g = d_grid_h;

    PointCtx cA = point_setup(points, pA, l);
    PointCtx cB = hasB ? point_setup(points, pB, l) : cA;

    // issue all 8 gathers up front (MLP=8)
    uint4 qA[4], qB[4];
    #pragma unroll
    for (int i = 0; i < 4; i++) qA[i] = ldg_el(g + cA.base[i], pol);
    #pragma unroll
    for (int i = 0; i < 4; i++) qB[i] = ldg_el(g + cB.base[i], pol);

    int slot = ((l & 1) << 1) | (l >> 1);

    float4 rA = point_combine(qA, cA, l);
    __stwt(&out[pA * 4 + slot], rA);             // write-through: no L2 allocate

    float4 rB = point_combine(qB, cB, l);
    if (hasB) __stwt(&out[pB * 4 + slot], rB);
}

extern "C" void kernel_launch(void* const* d_in, const int* in_sizes, int n_in,
                              void* d_out, int out_size) {
    const float*  points = (const float*)d_in[0];    // (N,3) fp32
    const float4* values = (const float4*)d_in[1];   // (128,128,128,16) fp32
    float4* out = (float4*)d_out;

    int n = in_sizes[0] / 3;
    int T = 256;

    convert_kernel<<<(NELEM4 + T - 1) / T, T>>>(values);

    int half = (n + 1) / 2;
    long long total = (long long)half * 4;
    interp_kernel<<<(int)((total + T - 1) / T), T>>>(points, out, n, half);
}

// round 13
// speedup vs baseline: 1.1109x; 1.1109x over previous
#include <cuda_runtime.h>
#include <cuda_fp16.h>

// NeuralVoxelField: trilinear interp of 2M random points into a 128^3 x16 grid.
//
// R12 = R10 interp (best so far) + convert pass improvements:
//  - convert handles 8 floats/thread and stores the fp16 grid with an
//    L2::evict_last cache hint: the 64MB scratch grid ENTERS L2 biased
//    resident (warm for interp) and, if never evicted, never writes back.
//  - interp: 1 point per 4 lanes, z-pair 16B gathers (evict_last), half2 x/y
//    lerp, fp32 z-combine via lane-pair shfl, evict-first output stores.

constexpr int Dg = 128, Hg = 128, Wg = 128, Cg = 16;
constexpr float INV_VOXEL = 20.0f;               // 1/0.05
constexpr int NVOX   = Dg * Hg * Wg;
constexpr int NHALF  = NVOX * Cg;                // 64MB of halves
constexpr int NELEM8 = NHALF / 8;                // 8 halves per convert thread

__device__ __align__(16) __half d_grid_h[NHALF];

__device__ __forceinline__ unsigned long long mk_evict_last_policy() {
    unsigned long long pol;
    asm("createpolicy.fractional.L2::evict_last.b64 %0, 1.0;" : "=l"(pol));
    return pol;
}

// ---- pass 1: fp32 grid -> fp16 scratch, stores biased evict_last ----
__global__ __launch_bounds__(256)
void convert_kernel(const float4* __restrict__ values) {
    int i = blockIdx.x * blockDim.x + threadIdx.x;
    if (i >= NELEM8) return;
    float4 v0 = __ldcs(&values[i * 2 + 0]);      // evict-first: read once
    float4 v1 = __ldcs(&values[i * 2 + 1]);
    uint4 u;
    __half2 h;
    h = __float22half2_rn(make_float2(v0.x, v0.y)); u.x = *(unsigned*)&h;
    h = __float22half2_rn(make_float2(v0.z, v0.w)); u.y = *(unsigned*)&h;
    h = __float22half2_rn(make_float2(v1.x, v1.y)); u.z = *(unsigned*)&h;
    h = __float22half2_rn(make_float2(v1.z, v1.w)); u.w = *(unsigned*)&h;
    unsigned long long pol = mk_evict_last_policy();
    asm volatile("st.global.L2::cache_hint.v4.u32 [%0], {%1,%2,%3,%4}, %5;"
                 :: "l"(d_grid_h + (size_t)i * 8),
                    "r"(u.x), "r"(u.y), "r"(u.z), "r"(u.w), "l"(pol)
                 : "memory");
}

// 16B gather with L2 evict-last cache hint (grid is the reuse set)
__device__ __forceinline__ uint4 ldg_el(const __half* p, unsigned long long pol) {
    uint4 q;
    asm volatile("ld.global.nc.L2::cache_hint.v4.u32 {%0,%1,%2,%3}, [%4], %5;"
                 : "=r"(q.x), "=r"(q.y), "=r"(q.z), "=r"(q.w)
                 : "l"(p), "l"(pol));
    return q;
}

// out[i] = a[i] + (b[i]-a[i])*w   (4x half2)
__device__ __forceinline__ void lerp_h2x4(const uint4& a, const uint4& b,
                                          __half2 w, __half2* o) {
    const __half2* ah = reinterpret_cast<const __half2*>(&a);
    const __half2* bh = reinterpret_cast<const __half2*>(&b);
    #pragma unroll
    for (int i = 0; i < 4; i++)
        o[i] = __hfma2(__hsub2(bh[i], ah[i]), w, ah[i]);
}

__global__ __launch_bounds__(256, 6)
void interp_kernel(const float* __restrict__ points,
                   float4* __restrict__ out,     // (N,16) fp32 as float4
                   int n)
{
    int t = blockIdx.x * blockDim.x + threadIdx.x;
    int p = t >> 2;        // point index
    int l = t & 3;         // lane-in-point: z-level = l>>1, channel half = l&1
    if (p >= n) return;

    // 4 lanes of one point read the same 12B -> L1 broadcast; evict-first.
    float x = __ldcs(&points[p * 3 + 0]) * INV_VOXEL;
    float y = __ldcs(&points[p * 3 + 1]) * INV_VOXEL;
    float z = __ldcs(&points[p * 3 + 2]) * INV_VOXEL;

    int x0 = min(max(__float2int_rd(x), 0), Dg - 1);
    int y0 = min(max(__float2int_rd(y), 0), Hg - 1);
    int z0 = min(max(__float2int_rd(z), 0), Wg - 1);
    int x1 = min(x0 + 1, Dg - 1);
    int y1 = min(y0 + 1, Hg - 1);
    int zp = min(z0, Wg - 2);          // z-pair base (z0 or 126)

    float xd = x - (float)x0;
    float yd = y - (float)y0;
    float zd = z - (float)z0;

    // z-pair weights: normally (1-zd, zd); clamped z0==127 -> (0, 1)
    float w1 = (z0 == Wg - 1) ? 1.0f : zd;
    int   v  = l >> 1;                  // my z-level within the pair
    float wa = v ? w1 : (1.0f - w1);    // my z-weight

    // half-element addresses: corner pair base + lane chunk (l*8 halves = 16B)
    int zb  = zp * Cg + l * 8;
    int a00 = ((x0 * Hg + y0) * Wg) * Cg + zb;
    int a01 = ((x0 * Hg + y1) * Wg) * Cg + zb;
    int a10 = ((x1 * Hg + y0) * Wg) * Cg + zb;
    int a11 = ((x1 * Hg + y1) * Wg) * Cg + zb;

    unsigned long long pol = mk_evict_last_policy();
    const __half* g = d_grid_h;
    // 4 wide gathers, MLP=4, evict-last in L2
    uint4 q00 = ldg_el(g + a00, pol);
    uint4 q01 = ldg_el(g + a01, pol);
    uint4 q10 = ldg_el(g + a10, pol);
    uint4 q11 = ldg_el(g + a11, pol);

    __half2 yd2 = __float2half2_rn(yd);
    __half2 xd2 = __float2half2_rn(xd);

    // y-lerp (half2): corners -> two x-levels
    __half2 t0[4], t1[4];
    lerp_h2x4(q00, q01, yd2, t0);      // @x0
    lerp_h2x4(q10, q11, yd2, t1);      // @x1

    // x-lerp (half2), then fp32 + my z-weight
    float m[8];
    #pragma unroll
    for (int i = 0; i < 4; i++) {
        __half2 r = __hfma2(__hsub2(t1[i], t0[i]), xd2, t0[i]);
        float2 f = __half22float2(r);
        m[i * 2 + 0] = f.x * wa;
        m[i * 2 + 1] = f.y * wa;
    }

    // sum the two z-levels (partner lane l^2 holds the other, pre-weighted)
    float c[8];
    #pragma unroll
    for (int i = 0; i < 8; i++)
        c[i] = m[i] + __shfl_xor_sync(0xffffffffu, m[i], 2);

    // lanes (0,2) hold ch0-7, lanes (1,3) hold ch8-15; each stores 4 channels:
    //   lane0->slot0 (ch0-3), lane2->slot1 (ch4-7),
    //   lane1->slot2 (ch8-11), lane3->slot3 (ch12-15)
    int slot = ((l & 1) << 1) | v;
    const float* s = c + v * 4;
    __stcs(&out[p * 4 + slot], make_float4(s[0], s[1], s[2], s[3]));
}

extern "C" void kernel_launch(void* const* d_in, const int* in_sizes, int n_in,
                              void* d_out, int out_size) {
    const float*  points = (const float*)d_in[0];    // (N,3) fp32
    const float4* values = (const float4*)d_in[1];   // (128,128,128,16) fp32
    float4* out = (float4*)d_out;

    int n = in_sizes[0] / 3;
    int T = 256;

    convert_kernel<<<(NELEM8 + T - 1) / T, T>>>(values);

    long long total = (long long)n * 4;
    interp_kernel<<<(int)((total + T - 1) / T), T>>>(points, out, n);
}

// round 14
// speedup vs baseline: 1.1159x; 1.0045x over previous
#include <cuda_runtime.h>
#include <cuda_fp16.h>

// NeuralVoxelField: trilinear interp of 2M random points into a 128^3 x16 grid.
//
// R13 = R12 + interp latency fixes:
//  1. __launch_bounds__(256,8): lift the self-imposed 75% occupancy cap
//     (regs=29 fits 2048 threads/SM) -> more in-flight gathers.
//  2. z-combine uses 4 shuffles instead of 8: pre-select the half each lane
//     keeps vs. sends (shfl_xor symmetry), halving the SHFL chain.
// Convert pass unchanged: 8 floats/thread, evict_last-hinted fp16 stores.

constexpr int Dg = 128, Hg = 128, Wg = 128, Cg = 16;
constexpr float INV_VOXEL = 20.0f;               // 1/0.05
constexpr int NVOX   = Dg * Hg * Wg;
constexpr int NHALF  = NVOX * Cg;                // 64MB of halves
constexpr int NELEM8 = NHALF / 8;

__device__ __align__(16) __half d_grid_h[NHALF];

__device__ __forceinline__ unsigned long long mk_evict_last_policy() {
    unsigned long long pol;
    asm("createpolicy.fractional.L2::evict_last.b64 %0, 1.0;" : "=l"(pol));
    return pol;
}

// ---- pass 1: fp32 grid -> fp16 scratch, stores biased evict_last ----
__global__ __launch_bounds__(256)
void convert_kernel(const float4* __restrict__ values) {
    int i = blockIdx.x * blockDim.x + threadIdx.x;
    if (i >= NELEM8) return;
    float4 v0 = __ldcs(&values[i * 2 + 0]);      // evict-first: read once
    float4 v1 = __ldcs(&values[i * 2 + 1]);
    uint4 u;
    __half2 h;
    h = __float22half2_rn(make_float2(v0.x, v0.y)); u.x = *(unsigned*)&h;
    h = __float22half2_rn(make_float2(v0.z, v0.w)); u.y = *(unsigned*)&h;
    h = __float22half2_rn(make_float2(v1.x, v1.y)); u.z = *(unsigned*)&h;
    h = __float22half2_rn(make_float2(v1.z, v1.w)); u.w = *(unsigned*)&h;
    unsigned long long pol = mk_evict_last_policy();
    asm volatile("st.global.L2::cache_hint.v4.u32 [%0], {%1,%2,%3,%4}, %5;"
                 :: "l"(d_grid_h + (size_t)i * 8),
                    "r"(u.x), "r"(u.y), "r"(u.z), "r"(u.w), "l"(pol)
                 : "memory");
}

// 16B gather with L2 evict-last cache hint (grid is the reuse set)
__device__ __forceinline__ uint4 ldg_el(const __half* p, unsigned long long pol) {
    uint4 q;
    asm volatile("ld.global.nc.L2::cache_hint.v4.u32 {%0,%1,%2,%3}, [%4], %5;"
                 : "=r"(q.x), "=r"(q.y), "=r"(q.z), "=r"(q.w)
                 : "l"(p), "l"(pol));
    return q;
}

// out[i] = a[i] + (b[i]-a[i])*w   (4x half2)
__device__ __forceinline__ void lerp_h2x4(const uint4& a, const uint4& b,
                                          __half2 w, __half2* o) {
    const __half2* ah = reinterpret_cast<const __half2*>(&a);
    const __half2* bh = reinterpret_cast<const __half2*>(&b);
    #pragma unroll
    for (int i = 0; i < 4; i++)
        o[i] = __hfma2(__hsub2(bh[i], ah[i]), w, ah[i]);
}

__global__ __launch_bounds__(256, 8)
void interp_kernel(const float* __restrict__ points,
                   float4* __restrict__ out,     // (N,16) fp32 as float4
                   int n)
{
    int t = blockIdx.x * blockDim.x + threadIdx.x;
    int p = t >> 2;        // point index
    int l = t & 3;         // lane-in-point: z-level = l>>1, channel half = l&1
    if (p >= n) return;

    // 4 lanes of one point read the same 12B -> L1 broadcast; evict-first.
    float x = __ldcs(&points[p * 3 + 0]) * INV_VOXEL;
    float y = __ldcs(&points[p * 3 + 1]) * INV_VOXEL;
    float z = __ldcs(&points[p * 3 + 2]) * INV_VOXEL;

    int x0 = min(max(__float2int_rd(x), 0), Dg - 1);
    int y0 = min(max(__float2int_rd(y), 0), Hg - 1);
    int z0 = min(max(__float2int_rd(z), 0), Wg - 1);
    int x1 = min(x0 + 1, Dg - 1);
    int y1 = min(y0 + 1, Hg - 1);
    int zp = min(z0, Wg - 2);          // z-pair base (z0 or 126)

    float xd = x - (float)x0;
    float yd = y - (float)y0;
    float zd = z - (float)z0;

    // z-pair weights: normally (1-zd, zd); clamped z0==127 -> (0, 1)
    float w1 = (z0 == Wg - 1) ? 1.0f : zd;
    bool  v  = (l >> 1) != 0;           // my z-level within the pair
    float wa = v ? w1 : (1.0f - w1);    // my z-weight

    // half-element addresses: corner pair base + lane chunk (l*8 halves = 16B)
    int zb  = zp * Cg + l * 8;
    int a00 = ((x0 * Hg + y0) * Wg) * Cg + zb;
    int a01 = ((x0 * Hg + y1) * Wg) * Cg + zb;
    int a10 = ((x1 * Hg + y0) * Wg) * Cg + zb;
    int a11 = ((x1 * Hg + y1) * Wg) * Cg + zb;

    unsigned long long pol = mk_evict_last_policy();
    const __half* g = d_grid_h;
    // 4 wide gathers, MLP=4, evict-last in L2
    uint4 q00 = ldg_el(g + a00, pol);
    uint4 q01 = ldg_el(g + a01, pol);
    uint4 q10 = ldg_el(g + a10, pol);
    uint4 q11 = ldg_el(g + a11, pol);

    __half2 yd2 = __float2half2_rn(yd);
    __half2 xd2 = __float2half2_rn(xd);

    // y-lerp (half2): corners -> two x-levels
    __half2 t0[4], t1[4];
    lerp_h2x4(q00, q01, yd2, t0);      // @x0
    lerp_h2x4(q10, q11, yd2, t1);      // @x1

    // x-lerp (half2), then fp32 + my z-weight
    float m[8];
    #pragma unroll
    for (int i = 0; i < 4; i++) {
        __half2 r = __hfma2(__hsub2(t1[i], t0[i]), xd2, t0[i]);
        float2 f = __half22float2(r);
        m[i * 2 + 0] = f.x * wa;
        m[i * 2 + 1] = f.y * wa;
    }

    // z-combine with 4 shuffles: lane keeps the half it will store and sends
    // the half its partner (l^2) stores; shfl_xor symmetry delivers exactly
    // the partner's weighted values for our half.
    float keep[4], send[4];
    #pragma unroll
    for (int j = 0; j < 4; j++) {
        keep[j] = v ? m[4 + j] : m[j];
        send[j] = v ? m[j] : m[4 + j];
    }
    float res[4];
    #pragma unroll
    for (int j = 0; j < 4; j++)
        res[j] = keep[j] + __shfl_xor_sync(0xffffffffu, send[j], 2);

    // lane0->slot0 (ch0-3), lane2->slot1 (ch4-7),
    // lane1->slot2 (ch8-11), lane3->slot3 (ch12-15)
    int slot = ((l & 1) << 1) | (int)v;
    __stcs(&out[p * 4 + slot], make_float4(res[0], res[1], res[2], res[3]));
}

extern "C" void kernel_launch(void* const* d_in, const int* in_sizes, int n_in,
                              void* d_out, int out_size) {
    const float*  points = (const float*)d_in[0];    // (N,3) fp32
    const float4* values = (const float4*)d_in[1];   // (128,128,128,16) fp32
    float4* out = (float4*)d_out;

    int n = in_sizes[0] / 3;
    int T = 256;

    convert_kernel<<<(NELEM8 + T - 1) / T, T>>>(values);

    long long total = (long long)n * 4;
    interp_kernel<<<(int)((total + T - 1) / T), T>>>(points, out, n);
}

// round 15
// speedup vs baseline: 1.1360x; 1.0180x over previous
#include <cuda_runtime.h>
#include <cuda_fp16.h>

// NeuralVoxelField: trilinear interp of 2M random points into a 128^3 x16 grid.
//
// R14 = R13 minus dead weight, plus coalesced point loads:
//  - warp's 8 points (96B of coords) loaded by 24 lanes in ONE coalesced LDG,
//    distributed via 3 shfl_idx (was: 3 broadcast LDGs per warp).
//  - gathers are plain __ldg (evict-last policy proven a no-op in R11-13).
//  - lower-bound clamps dropped (inputs are in-range by construction; x1/zp
//    upper clamps kept - those do fire).
//  - tail warps: all lanes run (shuffles need full warp), store predicated.
// Convert pass unchanged (8 floats/thread, evict_last-hinted fp16 stores).

constexpr int Dg = 128, Hg = 128, Wg = 128, Cg = 16;
constexpr float INV_VOXEL = 20.0f;               // 1/0.05
constexpr int NVOX   = Dg * Hg * Wg;
constexpr int NHALF  = NVOX * Cg;                // 64MB of halves
constexpr int NELEM8 = NHALF / 8;

__device__ __align__(16) __half d_grid_h[NHALF];

__device__ __forceinline__ unsigned long long mk_evict_last_policy() {
    unsigned long long pol;
    asm("createpolicy.fractional.L2::evict_last.b64 %0, 1.0;" : "=l"(pol));
    return pol;
}

// ---- pass 1: fp32 grid -> fp16 scratch, stores biased evict_last ----
__global__ __launch_bounds__(256)
void convert_kernel(const float4* __restrict__ values) {
    int i = blockIdx.x * blockDim.x + threadIdx.x;
    if (i >= NELEM8) return;
    float4 v0 = __ldcs(&values[i * 2 + 0]);      // evict-first: read once
    float4 v1 = __ldcs(&values[i * 2 + 1]);
    uint4 u;
    __half2 h;
    h = __float22half2_rn(make_float2(v0.x, v0.y)); u.x = *(unsigned*)&h;
    h = __float22half2_rn(make_float2(v0.z, v0.w)); u.y = *(unsigned*)&h;
    h = __float22half2_rn(make_float2(v1.x, v1.y)); u.z = *(unsigned*)&h;
    h = __float22half2_rn(make_float2(v1.z, v1.w)); u.w = *(unsigned*)&h;
    unsigned long long pol = mk_evict_last_policy();
    asm volatile("st.global.L2::cache_hint.v4.u32 [%0], {%1,%2,%3,%4}, %5;"
                 :: "l"(d_grid_h + (size_t)i * 8),
                    "r"(u.x), "r"(u.y), "r"(u.z), "r"(u.w), "l"(pol)
                 : "memory");
}

// out[i] = a[i] + (b[i]-a[i])*w   (4x half2)
__device__ __forceinline__ void lerp_h2x4(const uint4& a, const uint4& b,
                                          __half2 w, __half2* o) {
    const __half2* ah = reinterpret_cast<const __half2*>(&a);
    const __half2* bh = reinterpret_cast<const __half2*>(&b);
    #pragma unroll
    for (int i = 0; i < 4; i++)
        o[i] = __hfma2(__hsub2(bh[i], ah[i]), w, ah[i]);
}

__global__ __launch_bounds__(256, 8)
void interp_kernel(const float* __restrict__ points,
                   float4* __restrict__ out,     // (N,16) fp32 as float4
                   int n)
{
    int tid = blockIdx.x * blockDim.x + threadIdx.x;
    int la  = threadIdx.x & 31;          // lane in warp
    int wb  = (tid & ~31) >> 2;          // first point of this warp (8/warp)
    int q   = la >> 2;                   // point-in-warp 0..7
    int l   = la & 3;                    // lane-in-point
    int p   = wb + q;                    // my point
    bool active = (p < n);

    // one coalesced 96B warp load of 8 points' coords, distributed by shuffle
    float fload = 0.0f;
    int ci = wb * 3 + la;
    if (la < 24 && ci < n * 3) fload = __ldcs(&points[ci]);
    float x = __shfl_sync(0xffffffffu, fload, q * 3 + 0) * INV_VOXEL;
    float y = __shfl_sync(0xffffffffu, fload, q * 3 + 1) * INV_VOXEL;
    float z = __shfl_sync(0xffffffffu, fload, q * 3 + 2) * INV_VOXEL;

    // inputs are in [0,128): lower clamps & x0/y0/z0 upper clamp never fire
    int x0 = __float2int_rd(x);
    int y0 = __float2int_rd(y);
    int z0 = __float2int_rd(z);
    int x1 = min(x0 + 1, Dg - 1);
    int y1 = min(y0 + 1, Hg - 1);
    int zp = min(z0, Wg - 2);            // z-pair base (z0 or 126)

    float xd = x - (float)x0;
    float yd = y - (float)y0;
    float zd = z - (float)z0;

    // z-pair weights: normally (1-zd, zd); clamped z0==127 -> (0, 1)
    float w1 = (z0 == Wg - 1) ? 1.0f : zd;
    bool  v  = (l >> 1) != 0;            // my z-level within the pair
    float wa = v ? w1 : (1.0f - w1);     // my z-weight

    // half-element addresses: corner pair base + lane chunk (l*8 halves = 16B)
    int zb  = zp * Cg + l * 8;
    int a00 = ((x0 * Hg + y0) * Wg) * Cg + zb;
    int a01 = ((x0 * Hg + y1) * Wg) * Cg + zb;
    int a10 = ((x1 * Hg + y0) * Wg) * Cg + zb;
    int a11 = ((x1 * Hg + y1) * Wg) * Cg + zb;

    const __half* g = d_grid_h;
    // 4 wide gathers, MLP=4 (inactive lanes gather index 0 - safe)
    uint4 q00 = __ldg((const uint4*)(g + a00));
    uint4 q01 = __ldg((const uint4*)(g + a01));
    uint4 q10 = __ldg((const uint4*)(g + a10));
    uint4 q11 = __ldg((const uint4*)(g + a11));

    __half2 yd2 = __float2half2_rn(yd);
    __half2 xd2 = __float2half2_rn(xd);

    // y-lerp (half2): corners -> two x-levels
    __half2 t0[4], t1[4];
    lerp_h2x4(q00, q01, yd2, t0);        // @x0
    lerp_h2x4(q10, q11, yd2, t1);        // @x1

    // x-lerp (half2), then fp32 + my z-weight
    float m[8];
    #pragma unroll
    for (int i = 0; i < 4; i++) {
        __half2 r = __hfma2(__hsub2(t1[i], t0[i]), xd2, t0[i]);
        float2 f = __half22float2(r);
        m[i * 2 + 0] = f.x * wa;
        m[i * 2 + 1] = f.y * wa;
    }

    // z-combine with 4 shuffles: keep the half we store, send the half the
    // partner (l^2) stores; full warp participates (tail-safe).
    float keep[4], send[4];
    #pragma unroll
    for (int j = 0; j < 4; j++) {
        keep[j] = v ? m[4 + j] : m[j];
        send[j] = v ? m[j] : m[4 + j];
    }
    float res[4];
    #pragma unroll
    for (int j = 0; j < 4; j++)
        res[j] = keep[j] + __shfl_xor_sync(0xffffffffu, send[j], 2);

    // lane0->slot0 (ch0-3), lane2->slot1 (ch4-7),
    // lane1->slot2 (ch8-11), lane3->slot3 (ch12-15)
    int slot = ((l & 1) << 1) | (int)v;
    if (active)
        __stcs(&out[p * 4 + slot], make_float4(res[0], res[1], res[2], res[3]));
}

extern "C" void kernel_launch(void* const* d_in, const int* in_sizes, int n_in,
                              void* d_out, int out_size) {
    const float*  points = (const float*)d_in[0];    // (N,3) fp32
    const float4* values = (const float4*)d_in[1];   // (128,128,128,16) fp32
    float4* out = (float4*)d_out;

    int n = in_sizes[0] / 3;
    int T = 256;

    convert_kernel<<<(NELEM8 + T - 1) / T, T>>>(values);

    long long total = (long long)n * 4;
    interp_kernel<<<(int)((total + T - 1) / T), T>>>(points, out, n);
}

// round 16
// speedup vs baseline: 1.1585x; 1.0198x over previous
#include <cuda_runtime.h>
#include <cuda_fp16.h>

// NeuralVoxelField: trilinear interp of 2M random points into a 128^3 x16 grid.
//
// R15 = R14 + software-pipelined grid-stride interp:
//  each warp processes 8-point chunks in a grid-stride loop and PREFETCHES the
//  next chunk's 96B of coords (one coalesced LDG) before processing the
//  current chunk. This removes the serial [coord-load -> gather-load] latency
//  chain (~2x DRAM latency per chunk) that set R14's equilibrium.
// Everything else unchanged: fp16 grid scratch (64MB), z-pair 16B gathers,
// half2 x/y lerp, 4-shuffle z-combine, evict-first outputs; convert pass with
// 8 floats/thread + evict_last-hinted stores.

constexpr int Dg = 128, Hg = 128, Wg = 128, Cg = 16;
constexpr float INV_VOXEL = 20.0f;               // 1/0.05
constexpr int NVOX   = Dg * Hg * Wg;
constexpr int NHALF  = NVOX * Cg;                // 64MB of halves
constexpr int NELEM8 = NHALF / 8;

__device__ __align__(16) __half d_grid_h[NHALF];

__device__ __forceinline__ unsigned long long mk_evict_last_policy() {
    unsigned long long pol;
    asm("createpolicy.fractional.L2::evict_last.b64 %0, 1.0;" : "=l"(pol));
    return pol;
}

// ---- pass 1: fp32 grid -> fp16 scratch, stores biased evict_last ----
__global__ __launch_bounds__(256)
void convert_kernel(const float4* __restrict__ values) {
    int i = blockIdx.x * blockDim.x + threadIdx.x;
    if (i >= NELEM8) return;
    float4 v0 = __ldcs(&values[i * 2 + 0]);      // evict-first: read once
    float4 v1 = __ldcs(&values[i * 2 + 1]);
    uint4 u;
    __half2 h;
    h = __float22half2_rn(make_float2(v0.x, v0.y)); u.x = *(unsigned*)&h;
    h = __float22half2_rn(make_float2(v0.z, v0.w)); u.y = *(unsigned*)&h;
    h = __float22half2_rn(make_float2(v1.x, v1.y)); u.z = *(unsigned*)&h;
    h = __float22half2_rn(make_float2(v1.z, v1.w)); u.w = *(unsigned*)&h;
    unsigned long long pol = mk_evict_last_policy();
    asm volatile("st.global.L2::cache_hint.v4.u32 [%0], {%1,%2,%3,%4}, %5;"
                 :: "l"(d_grid_h + (size_t)i * 8),
                    "r"(u.x), "r"(u.y), "r"(u.z), "r"(u.w), "l"(pol)
                 : "memory");
}

// out[i] = a[i] + (b[i]-a[i])*w   (4x half2)
__device__ __forceinline__ void lerp_h2x4(const uint4& a, const uint4& b,
                                          __half2 w, __half2* o) {
    const __half2* ah = reinterpret_cast<const __half2*>(&a);
    const __half2* bh = reinterpret_cast<const __half2*>(&b);
    #pragma unroll
    for (int i = 0; i < 4; i++)
        o[i] = __hfma2(__hsub2(bh[i], ah[i]), w, ah[i]);
}

// process one 8-point chunk; 'fload' holds this warp-chunk's coalesced coords
__device__ __forceinline__ void process_chunk(float fload, int pbase, int q,
                                              int l, bool v, int n,
                                              float4* __restrict__ out) {
    int p = pbase + q;

    float x = __shfl_sync(0xffffffffu, fload, q * 3 + 0) * INV_VOXEL;
    float y = __shfl_sync(0xffffffffu, fload, q * 3 + 1) * INV_VOXEL;
    float z = __shfl_sync(0xffffffffu, fload, q * 3 + 2) * INV_VOXEL;

    // inputs are in [0,128): only the +1 / pair upper clamps can fire
    int x0 = __float2int_rd(x);
    int y0 = __float2int_rd(y);
    int z0 = __float2int_rd(z);
    int x1 = min(x0 + 1, Dg - 1);
    int y1 = min(y0 + 1, Hg - 1);
    int zp = min(z0, Wg - 2);

    float xd = x - (float)x0;
    float yd = y - (float)y0;
    float zd = z - (float)z0;

    float w1 = (z0 == Wg - 1) ? 1.0f : zd;
    float wa = v ? w1 : (1.0f - w1);

    int zb  = zp * Cg + l * 8;
    int a00 = ((x0 * Hg + y0) * Wg) * Cg + zb;
    int a01 = ((x0 * Hg + y1) * Wg) * Cg + zb;
    int a10 = ((x1 * Hg + y0) * Wg) * Cg + zb;
    int a11 = ((x1 * Hg + y1) * Wg) * Cg + zb;

    const __half* g = d_grid_h;
    uint4 q00 = __ldg((const uint4*)(g + a00));
    uint4 q01 = __ldg((const uint4*)(g + a01));
    uint4 q10 = __ldg((const uint4*)(g + a10));
    uint4 q11 = __ldg((const uint4*)(g + a11));

    __half2 yd2 = __float2half2_rn(yd);
    __half2 xd2 = __float2half2_rn(xd);

    __half2 t0[4], t1[4];
    lerp_h2x4(q00, q01, yd2, t0);        // @x0
    lerp_h2x4(q10, q11, yd2, t1);        // @x1

    float m[8];
    #pragma unroll
    for (int i = 0; i < 4; i++) {
        __half2 r = __hfma2(__hsub2(t1[i], t0[i]), xd2, t0[i]);
        float2 f = __half22float2(r);
        m[i * 2 + 0] = f.x * wa;
        m[i * 2 + 1] = f.y * wa;
    }

    float keep[4], send[4];
    #pragma unroll
    for (int j = 0; j < 4; j++) {
        keep[j] = v ? m[4 + j] : m[j];
        send[j] = v ? m[j] : m[4 + j];
    }
    float res[4];
    #pragma unroll
    for (int j = 0; j < 4; j++)
        res[j] = keep[j] + __shfl_xor_sync(0xffffffffu, send[j], 2);

    int slot = ((l & 1) << 1) | (int)v;
    if (p < n)
        __stcs(&out[p * 4 + slot], make_float4(res[0], res[1], res[2], res[3]));
}

__global__ __launch_bounds__(256, 8)
void interp_kernel(const float* __restrict__ points,
                   float4* __restrict__ out,     // (N,16) fp32 as float4
                   int n, int nchunks)
{
    int la = threadIdx.x & 31;           // lane in warp
    int q  = la >> 2;                    // point-in-warp 0..7
    int l  = la & 3;                     // lane-in-point
    bool v = (l >> 1) != 0;              // my z-level

    int warpId = (blockIdx.x * blockDim.x + threadIdx.x) >> 5;
    int nwarps = (gridDim.x * blockDim.x) >> 5;
    int n3 = n * 3;

    int c = warpId;
    if (c >= nchunks) return;

    // prologue: load this chunk's coords
    float cur = 0.0f;
    {
        int ci = c * 24 + la;
        if (la < 24 && ci < n3) cur = __ldcs(&points[ci]);
    }

    for (; c < nchunks; ) {
        int cn = c + nwarps;
        // prefetch next chunk's coords before processing current
        float nxt = 0.0f;
        if (cn < nchunks) {
            int ci = cn * 24 + la;
            if (la < 24 && ci < n3) nxt = __ldcs(&points[ci]);
        }
        process_chunk(cur, c * 8, q, l, v, n, out);
        cur = nxt;
        c = cn;
    }
}

extern "C" void kernel_launch(void* const* d_in, const int* in_sizes, int n_in,
                              void* d_out, int out_size) {
    const float*  points = (const float*)d_in[0];    // (N,3) fp32
    const float4* values = (const float4*)d_in[1];   // (128,128,128,16) fp32
    float4* out = (float4*)d_out;

    int n = in_sizes[0] / 3;
    int T = 256;

    convert_kernel<<<(NELEM8 + T - 1) / T, T>>>(values);

    int nchunks = (n + 7) / 8;           // 8 points per warp-chunk
    int blocks = 4096;                   // 32768 warps, ~8 chunks each
    interp_kernel<<<blocks, T>>>(points, out, n, nchunks);
}